// round 1
// baseline (speedup 1.0000x reference)
#include <cuda_runtime.h>
#include <math.h>

#define BSZ 1024
#define DIM 128
#define K2  256   // concatenated feature length

// Scratch (allocation-free rule: __device__ globals)
__device__ float gZt[K2 * BSZ];   // k-major: gZt[k*BSZ + row]
__device__ float gWt[K2 * BSZ];   // same, with first half negated
__device__ float gC[BSZ];         // (1-a)*||x_i||^2

// ---------------------------------------------------------------------------
// Prep: z = [s1*x, s2*e], w = [-s1*x, s2*e], written k-major via smem transpose
// grid (32, 4), block (32, 8): tile = 32 rows x 32 d
// ---------------------------------------------------------------------------
__global__ void prep_kernel(const float* __restrict__ x,
                            const float* __restrict__ dc,
                            const float* __restrict__ ap) {
    __shared__ float tg[32][33];
    __shared__ float th[32][33];
    const float a  = ap[0];
    const float s1 = sqrtf(2.0f * (1.0f - a));
    const float s2 = sqrtf(a);
    const int rb = blockIdx.x * 32;
    const int db = blockIdx.y * 32;
    const int tx = threadIdx.x, ty = threadIdx.y;

    #pragma unroll
    for (int i = ty; i < 32; i += 8) {
        const int row = rb + i;
        const int d   = db + tx;
        const float xv = x[row * DIM + d];
        const float ev = expf(1.0f - dc[row * DIM + d]);
        tg[i][tx] = s1 * xv;
        th[i][tx] = s2 * ev;
    }
    __syncthreads();
    #pragma unroll
    for (int i = ty; i < 32; i += 8) {
        const int k   = db + i;
        const int row = rb + tx;
        const float g = tg[tx][i];
        const float h = th[tx][i];
        gZt[k * BSZ + row]         =  g;
        gZt[(DIM + k) * BSZ + row] =  h;
        gWt[k * BSZ + row]         = -g;
        gWt[(DIM + k) * BSZ + row] =  h;
    }
}

// ---------------------------------------------------------------------------
// Row constants: gC[row] = (1-a) * sum_d x[row][d]^2
// grid 1024, block 128
// ---------------------------------------------------------------------------
__global__ void rowc_kernel(const float* __restrict__ x,
                            const float* __restrict__ ap) {
    const int row = blockIdx.x;
    float v = x[row * DIM + threadIdx.x];
    float s = v * v;
    #pragma unroll
    for (int o = 16; o; o >>= 1) s += __shfl_down_sync(0xffffffffu, s, o);
    __shared__ float ws[4];
    if ((threadIdx.x & 31) == 0) ws[threadIdx.x >> 5] = s;
    __syncthreads();
    if (threadIdx.x == 0) {
        const float a = ap[0];
        gC[row] = (1.0f - a) * (ws[0] + ws[1] + ws[2] + ws[3]);
    }
}

// ---------------------------------------------------------------------------
// GEMM + epilogue: S = Zt^T * Wt (K=256), out[i][j] = i==j ? 1 : D/(c_i+c_j+S)
// BM=BN=64, BK=64, 256 threads, 4x4 per thread. grid (16,16).
// ---------------------------------------------------------------------------
#define BM 64
#define BN 64
#define BK 64

__global__ void __launch_bounds__(256, 2)
gemm_kernel(float* __restrict__ out) {
    __shared__ float As[BK][BM];
    __shared__ float Bs[BK][BN];

    const int tid = threadIdx.x;
    const int tx  = tid & 15;          // output col group
    const int ty  = tid >> 4;          // output row group
    const int i0  = blockIdx.y * BM;
    const int j0  = blockIdx.x * BN;

    // loader mapping: 16 float4-columns x 16 k-rows per pass, 4 passes
    const int lc = tid & 15;
    const int lr = tid >> 4;

    float acc[4][4] = {};

    for (int k0 = 0; k0 < K2; k0 += BK) {
        #pragma unroll
        for (int p = 0; p < 4; p++) {
            const int k = lr + p * 16;
            const float4 av = *(const float4*)&gZt[(k0 + k) * BSZ + i0 + lc * 4];
            const float4 bv = *(const float4*)&gWt[(k0 + k) * BSZ + j0 + lc * 4];
            *(float4*)&As[k][lc * 4] = av;
            *(float4*)&Bs[k][lc * 4] = bv;
        }
        __syncthreads();

        #pragma unroll 8
        for (int k = 0; k < BK; k++) {
            float a[4], b[4];
            *(float4*)a = *(const float4*)&As[k][ty * 4];
            *(float4*)b = *(const float4*)&Bs[k][tx * 4];
            #pragma unroll
            for (int r = 0; r < 4; r++)
                #pragma unroll
                for (int c = 0; c < 4; c++)
                    acc[r][c] = fmaf(a[r], b[c], acc[r][c]);
        }
        __syncthreads();
    }

    // epilogue
    #pragma unroll
    for (int r = 0; r < 4; r++) {
        const int i = i0 + ty * 4 + r;
        const float ci = gC[i];
        float res[4];
        #pragma unroll
        for (int c = 0; c < 4; c++) {
            const int j = j0 + tx * 4 + c;
            const float denom = ci + gC[j] + acc[r][c];
            res[c] = (i == j) ? 1.0f : (float)DIM / denom;
        }
        *(float4*)&out[i * BSZ + j0 + tx * 4] =
            make_float4(res[0], res[1], res[2], res[3]);
    }
}

// ---------------------------------------------------------------------------
extern "C" void kernel_launch(void* const* d_in, const int* in_sizes, int n_in,
                              void* d_out, int out_size) {
    const float* x  = (const float*)d_in[0];
    const float* dc = (const float*)d_in[1];
    const float* ap = (const float*)d_in[2];
    float* out = (float*)d_out;

    prep_kernel<<<dim3(32, 4), dim3(32, 8)>>>(x, dc, ap);
    rowc_kernel<<<BSZ, DIM>>>(x, ap);
    gemm_kernel<<<dim3(BSZ / BN, BSZ / BM), 256>>>(out);
}

// round 3
// speedup vs baseline: 1.6867x; 1.6867x over previous
#include <cuda_runtime.h>
#include <cuda_bf16.h>
#include <cstdint>
#include <math.h>

#define BSZ 1024
#define DIM 128
#define K2  256     // concatenated feature length
#define STRIDE 264  // smem row pitch in bf16 (132 words; 132 mod 32 = 4 -> conflict-free frags)

// ---------------- scratch (__device__ globals; allocation-free rule) -------
__device__ __nv_bfloat16 gZhi[BSZ * K2];
__device__ __nv_bfloat16 gZlo[BSZ * K2];
__device__ __nv_bfloat16 gWhi[BSZ * K2];
__device__ __nv_bfloat16 gWlo[BSZ * K2];
__device__ float gC[BSZ];   // (1-a)*||x_i||^2

// ---------------------------------------------------------------------------
// Prep: g = s1*x (k 0..127), h = s2*exp(1-dc) (k 128..255); Z=[g,h], W=[-g,h]
// split into bf16 hi/lo, row-major k-contiguous.  One warp = one row; fused
// row-norm reduction into gC.  grid 128, block 256.
// ---------------------------------------------------------------------------
__device__ __forceinline__ void split4(const float v[4], __nv_bfloat16* hi, __nv_bfloat16* lo) {
    __nv_bfloat16 h[4], l[4];
#pragma unroll
    for (int i = 0; i < 4; i++) {
        h[i] = __float2bfloat16(v[i]);
        l[i] = __float2bfloat16(v[i] - __bfloat162float(h[i]));
    }
    *(uint2*)hi = *(uint2*)h;
    *(uint2*)lo = *(uint2*)l;
}

__global__ void __launch_bounds__(256)
prep_kernel(const float* __restrict__ x, const float* __restrict__ dc,
            const float* __restrict__ ap) {
    const int g   = blockIdx.x * 256 + threadIdx.x;
    const int row = g >> 5;
    const int d   = (g & 31) * 4;
    const float a  = ap[0];
    const float s1 = sqrtf(2.0f * (1.0f - a));
    const float s2 = sqrtf(a);

    const float4 xv = *(const float4*)&x[row * DIM + d];
    const float4 dv = *(const float4*)&dc[row * DIM + d];

    float gv[4] = { s1 * xv.x, s1 * xv.y, s1 * xv.z, s1 * xv.w };
    float ng[4] = { -gv[0], -gv[1], -gv[2], -gv[3] };
    float hv[4] = { s2 * expf(1.0f - dv.x), s2 * expf(1.0f - dv.y),
                    s2 * expf(1.0f - dv.z), s2 * expf(1.0f - dv.w) };

    const int ob = row * K2 + d;     // first half (x part)
    const int oh = ob + DIM;         // second half (e part)
    split4(gv, &gZhi[ob], &gZlo[ob]);
    split4(hv, &gZhi[oh], &gZlo[oh]);
    split4(ng, &gWhi[ob], &gWlo[ob]);
    split4(hv, &gWhi[oh], &gWlo[oh]);

    float s = xv.x * xv.x + xv.y * xv.y + xv.z * xv.z + xv.w * xv.w;
#pragma unroll
    for (int o = 16; o; o >>= 1) s += __shfl_down_sync(0xffffffffu, s, o);
    if ((threadIdx.x & 31) == 0) gC[row] = (1.0f - a) * s;
}

// ---------------------------------------------------------------------------
// mma.sync bf16 m16n8k16 (sm_80+ path; works on plain sm_100 target)
// ---------------------------------------------------------------------------
__device__ __forceinline__ void mma_bf16(float c[4],
                                         uint32_t a0, uint32_t a1, uint32_t a2, uint32_t a3,
                                         uint32_t b0, uint32_t b1) {
    asm volatile(
        "mma.sync.aligned.m16n8k16.row.col.f32.bf16.bf16.f32 "
        "{%0,%1,%2,%3}, {%4,%5,%6,%7}, {%8,%9}, {%0,%1,%2,%3};"
        : "+f"(c[0]), "+f"(c[1]), "+f"(c[2]), "+f"(c[3])
        : "r"(a0), "r"(a1), "r"(a2), "r"(a3), "r"(b0), "r"(b1));
}

// ---------------------------------------------------------------------------
// GEMM + epilogue.  CTA tile 128(m) x 64(n), full K=256 resident in smem.
// 8 warps in 4(m) x 2(n), warp tile 32x32 -> mfrags=2, nfrags=4.
// 3 terms: Ahi*Bhi + Ahi*Blo + Alo*Bhi, fp32 accum.
// Dynamic smem: Ahi|Alo (128x264 each) + Bhi|Blo (64x264 each) = 202752 B.
// ---------------------------------------------------------------------------
#define OFF_AHI 0
#define OFF_ALO (128 * STRIDE)
#define OFF_BHI (2 * 128 * STRIDE)
#define OFF_BLO (2 * 128 * STRIDE + 64 * STRIDE)
#define SMEM_ELEMS (2 * 128 * STRIDE + 2 * 64 * STRIDE)
#define SMEM_BYTES (SMEM_ELEMS * 2)

template <int ROWS>
__device__ __forceinline__ void load_tile(__nv_bfloat16* __restrict__ dst,
                                          const __nv_bfloat16* __restrict__ src,
                                          int row0, int tid) {
    constexpr int NCH = ROWS * 32;   // 16B chunks (8 bf16 each)
#pragma unroll
    for (int idx = tid; idx < NCH; idx += 256) {
        const int r = idx >> 5;
        const int c = idx & 31;
        *(uint4*)&dst[r * STRIDE + c * 8] = *(const uint4*)&src[(row0 + r) * K2 + c * 8];
    }
}

__global__ void __launch_bounds__(256, 1)
gemm_kernel(float* __restrict__ out) {
    extern __shared__ __align__(16) __nv_bfloat16 smem[];

    const int tid = threadIdx.x;
    const int wid = tid >> 5;
    const int lid = tid & 31;
    const int wm  = wid & 3;          // 0..3 -> m offset wm*32
    const int wn  = wid >> 2;         // 0..1 -> n offset wn*32
    const int g   = lid >> 2;         // 0..7
    const int t   = lid & 3;          // 0..3
    const int i0  = blockIdx.y * 128;
    const int j0  = blockIdx.x * 64;

    load_tile<128>(smem + OFF_AHI, gZhi, i0, tid);
    load_tile<128>(smem + OFF_ALO, gZlo, i0, tid);
    load_tile<64> (smem + OFF_BHI, gWhi, j0, tid);
    load_tile<64> (smem + OFF_BLO, gWlo, j0, tid);
    __syncthreads();

    float acc[2][4][4] = {};

    const __nv_bfloat16* Ah = smem + OFF_AHI + (wm * 32 + g) * STRIDE;
    const __nv_bfloat16* Al = smem + OFF_ALO + (wm * 32 + g) * STRIDE;
    const __nv_bfloat16* Bh = smem + OFF_BHI + (wn * 32 + g) * STRIDE;
    const __nv_bfloat16* Bl = smem + OFF_BLO + (wn * 32 + g) * STRIDE;

#pragma unroll 4
    for (int ks = 0; ks < 16; ks++) {
        const int ka = ks * 16 + t * 2;

        uint32_t ahi[2][4], alo[2][4], bhi[4][2], blo[4][2];
#pragma unroll
        for (int mf = 0; mf < 2; mf++) {
            const __nv_bfloat16* p = Ah + mf * 16 * STRIDE + ka;
            ahi[mf][0] = *(const uint32_t*)p;
            ahi[mf][1] = *(const uint32_t*)(p + 8 * STRIDE);
            ahi[mf][2] = *(const uint32_t*)(p + 8);
            ahi[mf][3] = *(const uint32_t*)(p + 8 * STRIDE + 8);
            const __nv_bfloat16* q = Al + mf * 16 * STRIDE + ka;
            alo[mf][0] = *(const uint32_t*)q;
            alo[mf][1] = *(const uint32_t*)(q + 8 * STRIDE);
            alo[mf][2] = *(const uint32_t*)(q + 8);
            alo[mf][3] = *(const uint32_t*)(q + 8 * STRIDE + 8);
        }
#pragma unroll
        for (int nf = 0; nf < 4; nf++) {
            const __nv_bfloat16* p = Bh + nf * 8 * STRIDE + ka;
            bhi[nf][0] = *(const uint32_t*)p;
            bhi[nf][1] = *(const uint32_t*)(p + 8);
            const __nv_bfloat16* q = Bl + nf * 8 * STRIDE + ka;
            blo[nf][0] = *(const uint32_t*)q;
            blo[nf][1] = *(const uint32_t*)(q + 8);
        }

#pragma unroll
        for (int mf = 0; mf < 2; mf++)
#pragma unroll
            for (int nf = 0; nf < 4; nf++) {
                mma_bf16(acc[mf][nf], ahi[mf][0], ahi[mf][1], ahi[mf][2], ahi[mf][3],
                         bhi[nf][0], bhi[nf][1]);
                mma_bf16(acc[mf][nf], ahi[mf][0], ahi[mf][1], ahi[mf][2], ahi[mf][3],
                         blo[nf][0], blo[nf][1]);
                mma_bf16(acc[mf][nf], alo[mf][0], alo[mf][1], alo[mf][2], alo[mf][3],
                         bhi[nf][0], bhi[nf][1]);
            }
    }

    // epilogue: out[i][j] = (i==j) ? 1 : DIM / (c_i + c_j + S_ij)
#pragma unroll
    for (int mf = 0; mf < 2; mf++) {
        const int ia = i0 + wm * 32 + mf * 16 + g;
        const int ib = ia + 8;
        const float cia = gC[ia];
        const float cib = gC[ib];
#pragma unroll
        for (int nf = 0; nf < 4; nf++) {
            const int j = j0 + wn * 32 + nf * 8 + t * 2;
            const float cj0 = gC[j];
            const float cj1 = gC[j + 1];
            const float* s = acc[mf][nf];

            float v00 = (ia == j)     ? 1.0f : (float)DIM / (cia + cj0 + s[0]);
            float v01 = (ia == j + 1) ? 1.0f : (float)DIM / (cia + cj1 + s[1]);
            float v10 = (ib == j)     ? 1.0f : (float)DIM / (cib + cj0 + s[2]);
            float v11 = (ib == j + 1) ? 1.0f : (float)DIM / (cib + cj1 + s[3]);

            *(float2*)&out[ia * BSZ + j] = make_float2(v00, v01);
            *(float2*)&out[ib * BSZ + j] = make_float2(v10, v11);
        }
    }
}

// ---------------------------------------------------------------------------
extern "C" void kernel_launch(void* const* d_in, const int* in_sizes, int n_in,
                              void* d_out, int out_size) {
    const float* x  = (const float*)d_in[0];
    const float* dc = (const float*)d_in[1];
    const float* ap = (const float*)d_in[2];
    float* out = (float*)d_out;

    cudaFuncSetAttribute(gemm_kernel, cudaFuncAttributeMaxDynamicSharedMemorySize, SMEM_BYTES);

    prep_kernel<<<128, 256>>>(x, dc, ap);
    gemm_kernel<<<dim3(16, 8), 256, SMEM_BYTES>>>(out);
}

// round 4
// speedup vs baseline: 1.8421x; 1.0921x over previous
#include <cuda_runtime.h>
#include <cuda_bf16.h>
#include <cstdint>
#include <math.h>

#define BSZ 1024
#define DIM 128
#define K2  256     // concatenated feature length

// ---------------- scratch (__device__ globals; allocation-free rule) -------
__device__ __nv_bfloat16 gZhi[BSZ * K2];
__device__ __nv_bfloat16 gZlo[BSZ * K2];
__device__ __nv_bfloat16 gWhi[BSZ * K2];
__device__ __nv_bfloat16 gWlo[BSZ * K2];
__device__ float gC[BSZ];   // (1-a)*||x_i||^2

// ---------------- helpers --------------------------------------------------
__device__ __forceinline__ uint32_t smem_u32(const void* p) {
    uint32_t a;
    asm("{ .reg .u64 t; cvta.to.shared.u64 t, %1; cvt.u32.u64 %0, t; }"
        : "=r"(a) : "l"(p));
    return a;
}
#define LDSM4(r0, r1, r2, r3, addr) \
    asm volatile("ldmatrix.sync.aligned.m8n8.x4.shared.b16 {%0,%1,%2,%3}, [%4];" \
                 : "=r"(r0), "=r"(r1), "=r"(r2), "=r"(r3) : "r"(addr))
#define CP16(dst, src) \
    asm volatile("cp.async.cg.shared.global [%0], [%1], 16;" :: "r"(dst), "l"(src))
#define CP_COMMIT() asm volatile("cp.async.commit_group;" ::: "memory")
#define CP_WAIT(n)  asm volatile("cp.async.wait_group %0;" :: "n"(n) : "memory")

__device__ __forceinline__ void mma_bf16(float c[4],
                                         uint32_t a0, uint32_t a1, uint32_t a2, uint32_t a3,
                                         uint32_t b0, uint32_t b1) {
    asm volatile(
        "mma.sync.aligned.m16n8k16.row.col.f32.bf16.bf16.f32 "
        "{%0,%1,%2,%3}, {%4,%5,%6,%7}, {%8,%9}, {%0,%1,%2,%3};"
        : "+f"(c[0]), "+f"(c[1]), "+f"(c[2]), "+f"(c[3])
        : "r"(a0), "r"(a1), "r"(a2), "r"(a3), "r"(b0), "r"(b1));
}

// ---------------------------------------------------------------------------
// Prep (unchanged from R3, passed): Z=[s1*x, s2*exp(1-dc)], W=[-s1*x, s2*e],
// bf16 hi/lo split, fused row-norm.  grid 128, block 256.
// ---------------------------------------------------------------------------
__device__ __forceinline__ void split4(const float v[4], __nv_bfloat16* hi, __nv_bfloat16* lo) {
    __nv_bfloat16 h[4], l[4];
#pragma unroll
    for (int i = 0; i < 4; i++) {
        h[i] = __float2bfloat16(v[i]);
        l[i] = __float2bfloat16(v[i] - __bfloat162float(h[i]));
    }
    *(uint2*)hi = *(uint2*)h;
    *(uint2*)lo = *(uint2*)l;
}

__global__ void __launch_bounds__(256)
prep_kernel(const float* __restrict__ x, const float* __restrict__ dc,
            const float* __restrict__ ap) {
    const int g   = blockIdx.x * 256 + threadIdx.x;
    const int row = g >> 5;
    const int d   = (g & 31) * 4;
    const float a  = ap[0];
    const float s1 = sqrtf(2.0f * (1.0f - a));
    const float s2 = sqrtf(a);

    const float4 xv = *(const float4*)&x[row * DIM + d];
    const float4 dv = *(const float4*)&dc[row * DIM + d];

    float gv[4] = { s1 * xv.x, s1 * xv.y, s1 * xv.z, s1 * xv.w };
    float ng[4] = { -gv[0], -gv[1], -gv[2], -gv[3] };
    float hv[4] = { s2 * expf(1.0f - dv.x), s2 * expf(1.0f - dv.y),
                    s2 * expf(1.0f - dv.z), s2 * expf(1.0f - dv.w) };

    const int ob = row * K2 + d;
    const int oh = ob + DIM;
    split4(gv, &gZhi[ob], &gZlo[ob]);
    split4(hv, &gZhi[oh], &gZlo[oh]);
    split4(ng, &gWhi[ob], &gWlo[ob]);
    split4(hv, &gWhi[oh], &gWlo[oh]);

    float s = xv.x * xv.x + xv.y * xv.y + xv.z * xv.z + xv.w * xv.w;
#pragma unroll
    for (int o = 16; o; o >>= 1) s += __shfl_down_sync(0xffffffffu, s, o);
    if ((threadIdx.x & 31) == 0) gC[row] = (1.0f - a) * s;
}

// ---------------------------------------------------------------------------
// GEMM: CTA tile 128(m) x 64(n), K=256 in 2 chunks of 128, double-buffered
// smem filled with cp.async.  8 warps 4(m)x2(n), warp tile 32x32.
// Fragments via ldmatrix.x4, register double-buffered across k16 steps.
// 3 terms: Ahi*Bhi + Ahi*Blo + Alo*Bhi, fp32 accum.
//
// Per-chunk buffer (row pitch 272B = 128 bf16 + 16B pad; 272 % 128 == 16 ->
// LDSM 8-row phases conflict-free):
//   Ahi @0 (128x272=34816) | Alo @34816 | Bhi @69632 (64x272=17408) | Blo @87040
//   buffer = 104448 B, two buffers = 208896 B dynamic smem.
// ---------------------------------------------------------------------------
#define ROWB     272
#define OFF_ALO  34816
#define OFF_BHI  69632
#define OFF_BLO  87040
#define BUF_B    104448
#define SMEM_BYTES (2 * BUF_B)

__global__ void __launch_bounds__(256, 1)
gemm_kernel(float* __restrict__ out) {
    extern __shared__ __align__(16) char smem[];
    __shared__ float s_cj[64];

    const int tid = threadIdx.x;
    const int wid = tid >> 5;
    const int lid = tid & 31;
    const int wm  = wid & 3;           // m offset wm*32
    const int wn  = wid >> 2;          // n offset wn*32
    const int i0  = blockIdx.y * 128;
    const int j0  = blockIdx.x * 64;
    const uint32_t sb = smem_u32(smem);

    // ---- stage both K-chunks with cp.async (fire-and-forget) ----
#pragma unroll
    for (int c = 0; c < 2; c++) {
        const uint32_t bb = sb + c * BUF_B;
        const int ko = c * 128;
#pragma unroll
        for (int i = tid; i < 4096; i += 256) {       // A hi|lo: 128 rows x 16 chunks x 2
            const int h = i >> 11, r = (i >> 4) & 127, cc = i & 15;
            const __nv_bfloat16* src = (h ? gZlo : gZhi) + (i0 + r) * K2 + ko + cc * 8;
            CP16(bb + h * OFF_ALO + r * ROWB + cc * 16, src);
        }
#pragma unroll
        for (int i = tid; i < 2048; i += 256) {       // B hi|lo: 64 rows x 16 x 2
            const int h = i >> 10, r = (i >> 4) & 63, cc = i & 15;
            const __nv_bfloat16* src = (h ? gWlo : gWhi) + (j0 + r) * K2 + ko + cc * 8;
            CP16(bb + OFF_BHI + h * 17408 + r * ROWB + cc * 16, src);
        }
        CP_COMMIT();
    }

    if (tid < 64) s_cj[tid] = gC[j0 + tid];

    // ---- per-lane ldmatrix base addresses ----
    const uint32_t arow = lid & 15;
    const uint32_t acol = (lid >> 4) * 16;            // bytes
    const uint32_t brow = (lid & 7) | (((lid >> 4) & 1) << 3);
    const uint32_t bcol = ((lid >> 3) & 1) * 16;
    const uint32_t aHi = sb + (wm * 32 + arow) * ROWB + acol;
    const uint32_t aLo = aHi + OFF_ALO;
    const uint32_t bHi = sb + OFF_BHI + (wn * 32 + brow) * ROWB + bcol;
    const uint32_t bLo = bHi + 17408;

    float acc[2][4][4] = {};
    uint32_t F[2][32];   // [set][ ah0..7 | al0..7 | bh0..7 | bl0..7 ]

    auto ldf = [&](uint32_t* f, uint32_t ko) {
        LDSM4(f[0],  f[1],  f[2],  f[3],  aHi + ko);
        LDSM4(f[4],  f[5],  f[6],  f[7],  aHi + ko + 16 * ROWB);
        LDSM4(f[8],  f[9],  f[10], f[11], aLo + ko);
        LDSM4(f[12], f[13], f[14], f[15], aLo + ko + 16 * ROWB);
        LDSM4(f[16], f[17], f[18], f[19], bHi + ko);
        LDSM4(f[20], f[21], f[22], f[23], bHi + ko + 16 * ROWB);
        LDSM4(f[24], f[25], f[26], f[27], bLo + ko);
        LDSM4(f[28], f[29], f[30], f[31], bLo + ko + 16 * ROWB);
    };
    auto domma = [&](uint32_t* f) {
#pragma unroll
        for (int mf = 0; mf < 2; mf++) {
            uint32_t* ah = f + mf * 4;
            uint32_t* al = f + 8 + mf * 4;
#pragma unroll
            for (int nf = 0; nf < 4; nf++) {
                const uint32_t b0h = f[16 + nf * 2], b1h = f[17 + nf * 2];
                const uint32_t b0l = f[24 + nf * 2], b1l = f[25 + nf * 2];
                mma_bf16(acc[mf][nf], ah[0], ah[1], ah[2], ah[3], b0h, b1h);
                mma_bf16(acc[mf][nf], ah[0], ah[1], ah[2], ah[3], b0l, b1l);
                mma_bf16(acc[mf][nf], al[0], al[1], al[2], al[3], b0h, b1h);
            }
        }
    };

    // ---- chunk 0 ----
    CP_WAIT(1);
    __syncthreads();
    ldf(F[0], 0);
#pragma unroll
    for (int ks = 0; ks < 7; ks++) {
        ldf(F[(ks + 1) & 1], (uint32_t)(ks + 1) * 32);
        domma(F[ks & 1]);
    }
    domma(F[1]);

    // ---- chunk 1 ----
    CP_WAIT(0);
    __syncthreads();
    ldf(F[0], BUF_B);
#pragma unroll
    for (int ks = 0; ks < 7; ks++) {
        ldf(F[(ks + 1) & 1], BUF_B + (uint32_t)(ks + 1) * 32);
        domma(F[ks & 1]);
    }
    domma(F[1]);

    // ---- epilogue: out[i][j] = (i==j) ? 1 : DIM / (c_i + c_j + S_ij) ----
    const int g = lid >> 2;
    const int t = lid & 3;
#pragma unroll
    for (int mf = 0; mf < 2; mf++) {
        const int ia = i0 + wm * 32 + mf * 16 + g;
        const int ib = ia + 8;
        const float cia = gC[ia];
        const float cib = gC[ib];
#pragma unroll
        for (int nf = 0; nf < 4; nf++) {
            const int jc = wn * 32 + nf * 8 + t * 2;
            const int j  = j0 + jc;
            const float cj0 = s_cj[jc];
            const float cj1 = s_cj[jc + 1];
            const float* s = acc[mf][nf];

            float v00 = (ia == j)     ? 1.0f : (float)DIM / (cia + cj0 + s[0]);
            float v01 = (ia == j + 1) ? 1.0f : (float)DIM / (cia + cj1 + s[1]);
            float v10 = (ib == j)     ? 1.0f : (float)DIM / (cib + cj0 + s[2]);
            float v11 = (ib == j + 1) ? 1.0f : (float)DIM / (cib + cj1 + s[3]);

            *(float2*)&out[ia * BSZ + j] = make_float2(v00, v01);
            *(float2*)&out[ib * BSZ + j] = make_float2(v10, v11);
        }
    }
}

// ---------------------------------------------------------------------------
extern "C" void kernel_launch(void* const* d_in, const int* in_sizes, int n_in,
                              void* d_out, int out_size) {
    const float* x  = (const float*)d_in[0];
    const float* dc = (const float*)d_in[1];
    const float* ap = (const float*)d_in[2];
    float* out = (float*)d_out;

    cudaFuncSetAttribute(gemm_kernel, cudaFuncAttributeMaxDynamicSharedMemorySize, SMEM_BYTES);

    prep_kernel<<<128, 256>>>(x, dc, ap);
    gemm_kernel<<<dim3(16, 8), 256, SMEM_BYTES>>>(out);
}

// round 5
// speedup vs baseline: 1.8667x; 1.0133x over previous
#include <cuda_runtime.h>
#include <cuda_bf16.h>
#include <cstdint>
#include <math.h>

#define BSZ 1024
#define DIM 128
#define K2  256     // concatenated feature length

// ---------------- scratch (__device__ globals; allocation-free rule) -------
__device__ __nv_bfloat16 gZhi[BSZ * K2];
__device__ __nv_bfloat16 gZlo[BSZ * K2];
__device__ __nv_bfloat16 gWhi[BSZ * K2];
__device__ __nv_bfloat16 gWlo[BSZ * K2];
__device__ float gC[BSZ];   // (1-a)*||x_i||^2

// ---------------- helpers --------------------------------------------------
__device__ __forceinline__ uint32_t smem_u32(const void* p) {
    uint32_t a;
    asm("{ .reg .u64 t; cvta.to.shared.u64 t, %1; cvt.u32.u64 %0, t; }"
        : "=r"(a) : "l"(p));
    return a;
}
#define LDSM4(r0, r1, r2, r3, addr) \
    asm volatile("ldmatrix.sync.aligned.m8n8.x4.shared.b16 {%0,%1,%2,%3}, [%4];" \
                 : "=r"(r0), "=r"(r1), "=r"(r2), "=r"(r3) : "r"(addr))
#define CP16(dst, src) \
    asm volatile("cp.async.cg.shared.global [%0], [%1], 16;" :: "r"(dst), "l"(src))
#define CP_COMMIT() asm volatile("cp.async.commit_group;" ::: "memory")
#define CP_WAIT(n)  asm volatile("cp.async.wait_group %0;" :: "n"(n) : "memory")

__device__ __forceinline__ void mma_bf16(float c[4],
                                         uint32_t a0, uint32_t a1, uint32_t a2, uint32_t a3,
                                         uint32_t b0, uint32_t b1) {
    asm volatile(
        "mma.sync.aligned.m16n8k16.row.col.f32.bf16.bf16.f32 "
        "{%0,%1,%2,%3}, {%4,%5,%6,%7}, {%8,%9}, {%0,%1,%2,%3};"
        : "+f"(c[0]), "+f"(c[1]), "+f"(c[2]), "+f"(c[3])
        : "r"(a0), "r"(a1), "r"(a2), "r"(a3), "r"(b0), "r"(b1));
}

// ---------------------------------------------------------------------------
// Prep: Z=[s1*x, s2*exp(1-dc)], W=[-s1*x, s2*e], bf16 hi/lo split, fused
// row-norm.  grid 128, block 256.
// ---------------------------------------------------------------------------
__device__ __forceinline__ void split4(const float v[4], __nv_bfloat16* hi, __nv_bfloat16* lo) {
    __nv_bfloat16 h[4], l[4];
#pragma unroll
    for (int i = 0; i < 4; i++) {
        h[i] = __float2bfloat16(v[i]);
        l[i] = __float2bfloat16(v[i] - __bfloat162float(h[i]));
    }
    *(uint2*)hi = *(uint2*)h;
    *(uint2*)lo = *(uint2*)l;
}

__global__ void __launch_bounds__(256)
prep_kernel(const float* __restrict__ x, const float* __restrict__ dc,
            const float* __restrict__ ap) {
    const int g   = blockIdx.x * 256 + threadIdx.x;
    const int row = g >> 5;
    const int d   = (g & 31) * 4;
    const float a  = ap[0];
    const float s1 = sqrtf(2.0f * (1.0f - a));
    const float s2 = sqrtf(a);

    const float4 xv = *(const float4*)&x[row * DIM + d];
    const float4 dv = *(const float4*)&dc[row * DIM + d];

    float gv[4] = { s1 * xv.x, s1 * xv.y, s1 * xv.z, s1 * xv.w };
    float ng[4] = { -gv[0], -gv[1], -gv[2], -gv[3] };
    float hv[4] = { s2 * __expf(1.0f - dv.x), s2 * __expf(1.0f - dv.y),
                    s2 * __expf(1.0f - dv.z), s2 * __expf(1.0f - dv.w) };

    const int ob = row * K2 + d;
    const int oh = ob + DIM;
    split4(gv, &gZhi[ob], &gZlo[ob]);
    split4(hv, &gZhi[oh], &gZlo[oh]);
    split4(ng, &gWhi[ob], &gWlo[ob]);
    split4(hv, &gWhi[oh], &gWlo[oh]);

    float s = xv.x * xv.x + xv.y * xv.y + xv.z * xv.z + xv.w * xv.w;
#pragma unroll
    for (int o = 16; o; o >>= 1) s += __shfl_down_sync(0xffffffffu, s, o);
    if ((threadIdx.x & 31) == 0) gC[row] = (1.0f - a) * s;
}

// ---------------------------------------------------------------------------
// GEMM: CTA tile 128(m) x 64(n), 512 threads (16 warps, 4m x 4n, warp tile
// 32x16).  K=256 in 2 double-buffered cp.async chunks.  ldmatrix.x4 frags,
// register double-buffered.  3 terms: Ahi*Bhi + Ahi*Blo + Alo*Bhi.
// Row pitch 272 B (128 bf16 + 16B pad) -> LDSM phases conflict-free.
//   per chunk: Ahi @0 | Alo @34816 | Bhi @69632 | Blo @87040 ; 104448 B
// ---------------------------------------------------------------------------
#define ROWB     272
#define OFF_ALO  34816
#define OFF_BHI  69632
#define OFF_BLO  87040
#define BUF_B    104448
#define SMEM_BYTES (2 * BUF_B)

__global__ void __launch_bounds__(512, 1)
gemm_kernel(float* __restrict__ out) {
    extern __shared__ __align__(16) char smem[];
    __shared__ float s_cj[64];

    const int tid = threadIdx.x;
    const int wid = tid >> 5;
    const int lid = tid & 31;
    const int wm  = wid & 3;           // m offset wm*32
    const int wn  = wid >> 2;          // n offset wn*16
    const int i0  = blockIdx.y * 128;
    const int j0  = blockIdx.x * 64;
    const uint32_t sb = smem_u32(smem);

    // ---- stage both K-chunks with cp.async (fire-and-forget) ----
#pragma unroll
    for (int c = 0; c < 2; c++) {
        const uint32_t bb = sb + c * BUF_B;
        const int ko = c * 128;
#pragma unroll
        for (int i = tid; i < 4096; i += 512) {       // A hi|lo: 128 rows x 16 x 2
            const int h = i >> 11, r = (i >> 4) & 127, cc = i & 15;
            const __nv_bfloat16* src = (h ? gZlo : gZhi) + (i0 + r) * K2 + ko + cc * 8;
            CP16(bb + h * OFF_ALO + r * ROWB + cc * 16, src);
        }
#pragma unroll
        for (int i = tid; i < 2048; i += 512) {       // B hi|lo: 64 rows x 16 x 2
            const int h = i >> 10, r = (i >> 4) & 63, cc = i & 15;
            const __nv_bfloat16* src = (h ? gWlo : gWhi) + (j0 + r) * K2 + ko + cc * 8;
            CP16(bb + OFF_BHI + h * 17408 + r * ROWB + cc * 16, src);
        }
        CP_COMMIT();
    }

    if (tid < 64) s_cj[tid] = gC[j0 + tid];

    // ---- per-lane ldmatrix base addresses ----
    const uint32_t arow = lid & 15;
    const uint32_t acol = (lid >> 4) * 16;            // bytes
    const uint32_t brow = (lid & 7) | (((lid >> 4) & 1) << 3);
    const uint32_t bcol = ((lid >> 3) & 1) * 16;
    const uint32_t aHi = sb + (wm * 32 + arow) * ROWB + acol;
    const uint32_t aLo = aHi + OFF_ALO;
    const uint32_t bHi = sb + OFF_BHI + (wn * 16 + brow) * ROWB + bcol;
    const uint32_t bLo = bHi + 17408;

    float acc[2][2][4] = {};
    uint32_t F[2][24];   // [set][ ah0..7 | al0..7 | bh0..3 | bl0..3 ]

    auto ldf = [&](uint32_t* f, uint32_t ko) {
        LDSM4(f[0],  f[1],  f[2],  f[3],  aHi + ko);
        LDSM4(f[4],  f[5],  f[6],  f[7],  aHi + ko + 16 * ROWB);
        LDSM4(f[8],  f[9],  f[10], f[11], aLo + ko);
        LDSM4(f[12], f[13], f[14], f[15], aLo + ko + 16 * ROWB);
        LDSM4(f[16], f[17], f[18], f[19], bHi + ko);
        LDSM4(f[20], f[21], f[22], f[23], bLo + ko);
    };
    auto domma = [&](uint32_t* f) {
#pragma unroll
        for (int mf = 0; mf < 2; mf++) {
            uint32_t* ah = f + mf * 4;
            uint32_t* al = f + 8 + mf * 4;
#pragma unroll
            for (int nf = 0; nf < 2; nf++) {
                const uint32_t b0h = f[16 + nf * 2], b1h = f[17 + nf * 2];
                const uint32_t b0l = f[20 + nf * 2], b1l = f[21 + nf * 2];
                mma_bf16(acc[mf][nf], ah[0], ah[1], ah[2], ah[3], b0h, b1h);
                mma_bf16(acc[mf][nf], ah[0], ah[1], ah[2], ah[3], b0l, b1l);
                mma_bf16(acc[mf][nf], al[0], al[1], al[2], al[3], b0h, b1h);
            }
        }
    };

    // ---- chunk 0 ----
    CP_WAIT(1);
    __syncthreads();
    ldf(F[0], 0);
#pragma unroll
    for (int ks = 0; ks < 7; ks++) {
        ldf(F[(ks + 1) & 1], (uint32_t)(ks + 1) * 32);
        domma(F[ks & 1]);
    }
    domma(F[1]);

    // ---- chunk 1 ----
    CP_WAIT(0);
    __syncthreads();
    ldf(F[0], BUF_B);
#pragma unroll
    for (int ks = 0; ks < 7; ks++) {
        ldf(F[(ks + 1) & 1], BUF_B + (uint32_t)(ks + 1) * 32);
        domma(F[ks & 1]);
    }
    domma(F[1]);

    // ---- epilogue: out[i][j] = (i==j) ? 1 : DIM / (c_i + c_j + S_ij) ----
    const int g = lid >> 2;
    const int t = lid & 3;
#pragma unroll
    for (int mf = 0; mf < 2; mf++) {
        const int ia = i0 + wm * 32 + mf * 16 + g;
        const int ib = ia + 8;
        const float cia = gC[ia];
        const float cib = gC[ib];
#pragma unroll
        for (int nf = 0; nf < 2; nf++) {
            const int jc = wn * 16 + nf * 8 + t * 2;
            const int j  = j0 + jc;
            const float cj0 = s_cj[jc];
            const float cj1 = s_cj[jc + 1];
            const float* s = acc[mf][nf];

            float v00 = (ia == j)     ? 1.0f : (float)DIM / (cia + cj0 + s[0]);
            float v01 = (ia == j + 1) ? 1.0f : (float)DIM / (cia + cj1 + s[1]);
            float v10 = (ib == j)     ? 1.0f : (float)DIM / (cib + cj0 + s[2]);
            float v11 = (ib == j + 1) ? 1.0f : (float)DIM / (cib + cj1 + s[3]);

            *(float2*)&out[ia * BSZ + j] = make_float2(v00, v01);
            *(float2*)&out[ib * BSZ + j] = make_float2(v10, v11);
        }
    }
}

// ---------------------------------------------------------------------------
extern "C" void kernel_launch(void* const* d_in, const int* in_sizes, int n_in,
                              void* d_out, int out_size) {
    const float* x  = (const float*)d_in[0];
    const float* dc = (const float*)d_in[1];
    const float* ap = (const float*)d_in[2];
    float* out = (float*)d_out;

    cudaFuncSetAttribute(gemm_kernel, cudaFuncAttributeMaxDynamicSharedMemorySize, SMEM_BYTES);

    prep_kernel<<<128, 256>>>(x, dc, ap);
    gemm_kernel<<<dim3(16, 8), 512, SMEM_BYTES>>>(out);
}

// round 7
// speedup vs baseline: 2.3729x; 1.2712x over previous
#include <cuda_runtime.h>
#include <cuda_fp16.h>
#include <cstdint>
#include <math.h>

#define BSZ 1024
#define DIM 128
#define K2  256     // concatenated feature length

// ---------------- scratch (__device__ globals; allocation-free rule) -------
__device__ __half gZ[BSZ * K2];
__device__ __half gW[BSZ * K2];
__device__ float gC[BSZ];   // (1-a)*||x_i||^2

// ---------------- helpers --------------------------------------------------
__device__ __forceinline__ uint32_t smem_u32(const void* p) {
    uint32_t a;
    asm("{ .reg .u64 t; cvta.to.shared.u64 t, %1; cvt.u32.u64 %0, t; }"
        : "=r"(a) : "l"(p));
    return a;
}
#define LDSM4(r0, r1, r2, r3, addr) \
    asm volatile("ldmatrix.sync.aligned.m8n8.x4.shared.b16 {%0,%1,%2,%3}, [%4];" \
                 : "=r"(r0), "=r"(r1), "=r"(r2), "=r"(r3) : "r"(addr))
#define CP16(dst, src) \
    asm volatile("cp.async.cg.shared.global [%0], [%1], 16;" :: "r"(dst), "l"(src))
#define CP_COMMIT() asm volatile("cp.async.commit_group;" ::: "memory")
#define CP_WAIT(n)  asm volatile("cp.async.wait_group %0;" :: "n"(n) : "memory")

__device__ __forceinline__ void mma_f16(float c[4],
                                        uint32_t a0, uint32_t a1, uint32_t a2, uint32_t a3,
                                        uint32_t b0, uint32_t b1) {
    asm volatile(
        "mma.sync.aligned.m16n8k16.row.col.f32.f16.f16.f32 "
        "{%0,%1,%2,%3}, {%4,%5,%6,%7}, {%8,%9}, {%0,%1,%2,%3};"
        : "+f"(c[0]), "+f"(c[1]), "+f"(c[2]), "+f"(c[3])
        : "r"(a0), "r"(a1), "r"(a2), "r"(a3), "r"(b0), "r"(b1));
}

// ---------------------------------------------------------------------------
// Prep: Z=[s1*x, s2*exp(1-dc)], W=[-s1*x, s2*e] in fp16, fused row-norm.
// grid 128, block 256; one warp = one row.
// ---------------------------------------------------------------------------
__global__ void __launch_bounds__(256)
prep_kernel(const float* __restrict__ x, const float* __restrict__ dc,
            const float* __restrict__ ap) {
    const int g   = blockIdx.x * 256 + threadIdx.x;
    const int row = g >> 5;
    const int d   = (g & 31) * 4;
    const float a  = ap[0];
    const float s1 = sqrtf(2.0f * (1.0f - a));
    const float s2 = sqrtf(a);

    const float4 xv = *(const float4*)&x[row * DIM + d];
    const float4 dv = *(const float4*)&dc[row * DIM + d];

    const float g0 = s1 * xv.x, g1 = s1 * xv.y, g2 = s1 * xv.z, g3 = s1 * xv.w;
    const float h0 = s2 * __expf(1.0f - dv.x), h1 = s2 * __expf(1.0f - dv.y);
    const float h2 = s2 * __expf(1.0f - dv.z), h3 = s2 * __expf(1.0f - dv.w);

    const int ob = row * K2 + d;
    const int oh = ob + DIM;
    __half zb[4] = { __float2half_rn(g0),  __float2half_rn(g1),
                     __float2half_rn(g2),  __float2half_rn(g3) };
    __half wb[4] = { __float2half_rn(-g0), __float2half_rn(-g1),
                     __float2half_rn(-g2), __float2half_rn(-g3) };
    __half hb[4] = { __float2half_rn(h0),  __float2half_rn(h1),
                     __float2half_rn(h2),  __float2half_rn(h3) };
    *(uint2*)&gZ[ob] = *(uint2*)zb;
    *(uint2*)&gW[ob] = *(uint2*)wb;
    *(uint2*)&gZ[oh] = *(uint2*)hb;
    *(uint2*)&gW[oh] = *(uint2*)hb;

    float s = xv.x * xv.x + xv.y * xv.y + xv.z * xv.z + xv.w * xv.w;
#pragma unroll
    for (int o = 16; o; o >>= 1) s += __shfl_down_sync(0xffffffffu, s, o);
    if ((threadIdx.x & 31) == 0) gC[row] = (1.0f - a) * s;
}

// ---------------------------------------------------------------------------
// GEMM: CTA tile 128(m) x 64(n), 512 threads (16 warps, 4m x 4n, warp tile
// 32x16).  Single fp16 term, fp32 accum.  K=256 in 2 double-buffered
// cp.async chunks; ldmatrix.x4 frags, register double-buffered (12+12 regs).
// Row pitch 272 B (128 fp16 + 16B pad; 272 % 128 == 16 -> LDSM conflict-free)
//   per chunk: A @0 (128x272=34816) | B @34816 (64x272=17408) ; 52224 B
// ---------------------------------------------------------------------------
#define ROWB   272
#define OFF_B  34816
#define BUF_B  52224
#define SMEM_BYTES (2 * BUF_B)

__global__ void __launch_bounds__(512, 1)
gemm_kernel(float* __restrict__ out) {
    extern __shared__ __align__(16) char smem[];
    __shared__ float s_cj[64];

    const int tid = threadIdx.x;
    const int wid = tid >> 5;
    const int lid = tid & 31;
    const int wm  = wid & 3;           // m offset wm*32
    const int wn  = wid >> 2;          // n offset wn*16
    const int i0  = blockIdx.y * 128;
    const int j0  = blockIdx.x * 64;
    const uint32_t sb = smem_u32(smem);

    // ---- stage both K-chunks with cp.async (fire-and-forget) ----
#pragma unroll
    for (int c = 0; c < 2; c++) {
        const uint32_t bb = sb + c * BUF_B;
        const int ko = c * 128;
#pragma unroll
        for (int i = tid; i < 2048; i += 512) {       // A: 128 rows x 16 chunks
            const int r = i >> 4, cc = i & 15;
            CP16(bb + r * ROWB + cc * 16, gZ + (i0 + r) * K2 + ko + cc * 8);
        }
#pragma unroll
        for (int i = tid; i < 1024; i += 512) {       // B: 64 rows x 16 chunks
            const int r = i >> 4, cc = i & 15;
            CP16(bb + OFF_B + r * ROWB + cc * 16, gW + (j0 + r) * K2 + ko + cc * 8);
        }
        CP_COMMIT();
    }

    if (tid < 64) s_cj[tid] = gC[j0 + tid];

    // ---- per-lane ldmatrix base addresses ----
    const uint32_t arow = lid & 15;
    const uint32_t acol = (lid >> 4) * 16;            // bytes
    const uint32_t brow = (lid & 7) | (((lid >> 4) & 1) << 3);
    const uint32_t bcol = ((lid >> 3) & 1) * 16;
    const uint32_t aAd = sb + (wm * 32 + arow) * ROWB + acol;
    const uint32_t bAd = sb + OFF_B + (wn * 16 + brow) * ROWB + bcol;

    float acc[2][2][4] = {};
    uint32_t F[2][12];   // [set][ a0..7 | b0..3 ]

    auto ldf = [&](uint32_t* f, uint32_t ko) {
        LDSM4(f[0], f[1], f[2],  f[3],  aAd + ko);
        LDSM4(f[4], f[5], f[6],  f[7],  aAd + ko + 16 * ROWB);
        LDSM4(f[8], f[9], f[10], f[11], bAd + ko);
    };
    auto domma = [&](uint32_t* f) {
#pragma unroll
        for (int mf = 0; mf < 2; mf++) {
            uint32_t* a = f + mf * 4;
#pragma unroll
            for (int nf = 0; nf < 2; nf++)
                mma_f16(acc[mf][nf], a[0], a[1], a[2], a[3],
                        f[8 + nf * 2], f[9 + nf * 2]);
        }
    };

    // ---- chunk 0 ----
    CP_WAIT(1);
    __syncthreads();
    ldf(F[0], 0);
#pragma unroll
    for (int ks = 0; ks < 7; ks++) {
        ldf(F[(ks + 1) & 1], (uint32_t)(ks + 1) * 32);
        domma(F[ks & 1]);
    }
    domma(F[1]);

    // ---- chunk 1 ----
    CP_WAIT(0);
    __syncthreads();
    ldf(F[0], BUF_B);
#pragma unroll
    for (int ks = 0; ks < 7; ks++) {
        ldf(F[(ks + 1) & 1], BUF_B + (uint32_t)(ks + 1) * 32);
        domma(F[ks & 1]);
    }
    domma(F[1]);

    // ---- epilogue: out[i][j] = (i==j) ? 1 : DIM / (c_i + c_j + S_ij) ----
    const int g = lid >> 2;
    const int t = lid & 3;
#pragma unroll
    for (int mf = 0; mf < 2; mf++) {
        const int ia = i0 + wm * 32 + mf * 16 + g;
        const int ib = ia + 8;
        const float cia = gC[ia];
        const float cib = gC[ib];
#pragma unroll
        for (int nf = 0; nf < 2; nf++) {
            const int jc = wn * 16 + nf * 8 + t * 2;
            const int j  = j0 + jc;
            const float cj0 = s_cj[jc];
            const float cj1 = s_cj[jc + 1];
            const float* s = acc[mf][nf];

            float v00 = (ia == j)     ? 1.0f : (float)DIM / (cia + cj0 + s[0]);
            float v01 = (ia == j + 1) ? 1.0f : (float)DIM / (cia + cj1 + s[1]);
            float v10 = (ib == j)     ? 1.0f : (float)DIM / (cib + cj0 + s[2]);
            float v11 = (ib == j + 1) ? 1.0f : (float)DIM / (cib + cj1 + s[3]);

            *(float2*)&out[ia * BSZ + j] = make_float2(v00, v01);
            *(float2*)&out[ib * BSZ + j] = make_float2(v10, v11);
        }
    }
}

// ---------------------------------------------------------------------------
extern "C" void kernel_launch(void* const* d_in, const int* in_sizes, int n_in,
                              void* d_out, int out_size) {
    const float* x  = (const float*)d_in[0];
    const float* dc = (const float*)d_in[1];
    const float* ap = (const float*)d_in[2];
    float* out = (float*)d_out;

    cudaFuncSetAttribute(gemm_kernel, cudaFuncAttributeMaxDynamicSharedMemorySize, SMEM_BYTES);

    prep_kernel<<<128, 256>>>(x, dc, ap);
    gemm_kernel<<<dim3(16, 8), 512, SMEM_BYTES>>>(out);
}

// round 8
// speedup vs baseline: 2.5000x; 1.0536x over previous
#include <cuda_runtime.h>
#include <cuda_fp16.h>
#include <cstdint>
#include <math.h>

#define BSZ 1024
#define DIM 128
#define K2  256     // concatenated feature length

// ---------------- scratch (__device__ globals; allocation-free rule) -------
__device__ __half gZ[BSZ * K2];   // [s1*x | s2*exp(1-dc)] per row
__device__ float gC[BSZ];         // (1-a)*||x_i||^2

// ---------------- helpers --------------------------------------------------
__device__ __forceinline__ uint32_t smem_u32(const void* p) {
    uint32_t a;
    asm("{ .reg .u64 t; cvta.to.shared.u64 t, %1; cvt.u32.u64 %0, t; }"
        : "=r"(a) : "l"(p));
    return a;
}
#define LDSM4(r0, r1, r2, r3, addr) \
    asm volatile("ldmatrix.sync.aligned.m8n8.x4.shared.b16 {%0,%1,%2,%3}, [%4];" \
                 : "=r"(r0), "=r"(r1), "=r"(r2), "=r"(r3) : "r"(addr))
#define CP16(dst, src) \
    asm volatile("cp.async.cg.shared.global [%0], [%1], 16;" :: "r"(dst), "l"(src))
#define CP_COMMIT() asm volatile("cp.async.commit_group;" ::: "memory")
#define CP_WAIT(n)  asm volatile("cp.async.wait_group %0;" :: "n"(n) : "memory")

__device__ __forceinline__ void mma_f16(float c[4],
                                        uint32_t a0, uint32_t a1, uint32_t a2, uint32_t a3,
                                        uint32_t b0, uint32_t b1) {
    asm volatile(
        "mma.sync.aligned.m16n8k16.row.col.f32.f16.f16.f32 "
        "{%0,%1,%2,%3}, {%4,%5,%6,%7}, {%8,%9}, {%0,%1,%2,%3};"
        : "+f"(c[0]), "+f"(c[1]), "+f"(c[2]), "+f"(c[3])
        : "r"(a0), "r"(a1), "r"(a2), "r"(a3), "r"(b0), "r"(b1));
}

// ---------------------------------------------------------------------------
// Prep: gZ = [s1*x, s2*exp(1-dc)] fp16; fused row-norm into gC.
// grid 128, block 256; one warp = one row.
// ---------------------------------------------------------------------------
__global__ void __launch_bounds__(256)
prep_kernel(const float* __restrict__ x, const float* __restrict__ dc,
            const float* __restrict__ ap) {
    const int g   = blockIdx.x * 256 + threadIdx.x;
    const int row = g >> 5;
    const int d   = (g & 31) * 4;
    const float a  = ap[0];
    const float s1 = sqrtf(2.0f * (1.0f - a));
    const float s2 = sqrtf(a);

    const float4 xv = *(const float4*)&x[row * DIM + d];
    const float4 dv = *(const float4*)&dc[row * DIM + d];

    __half zb[4] = { __float2half_rn(s1 * xv.x), __float2half_rn(s1 * xv.y),
                     __float2half_rn(s1 * xv.z), __float2half_rn(s1 * xv.w) };
    __half hb[4] = { __float2half_rn(s2 * __expf(1.0f - dv.x)),
                     __float2half_rn(s2 * __expf(1.0f - dv.y)),
                     __float2half_rn(s2 * __expf(1.0f - dv.z)),
                     __float2half_rn(s2 * __expf(1.0f - dv.w)) };

    const int ob = row * K2 + d;
    *(uint2*)&gZ[ob]       = *(uint2*)zb;
    *(uint2*)&gZ[ob + DIM] = *(uint2*)hb;

    float s = xv.x * xv.x + xv.y * xv.y + xv.z * xv.z + xv.w * xv.w;
#pragma unroll
    for (int o = 16; o; o >>= 1) s += __shfl_down_sync(0xffffffffu, s, o);
    if ((threadIdx.x & 31) == 0) gC[row] = (1.0f - a) * s;
}

// ---------------------------------------------------------------------------
// GEMM: CTA tile 64(m) x 64(n), grid (16,16)=256 CTAs (2/SM, one wave),
// 256 threads (8 warps, 2m x 4n, warp tile 32x16).  Full K=256 resident in
// smem (A,B each 64x256 fp16, pitch 528B -> conflict-free LDSM), staged by
// cp.async in 2 commit groups (k<128, k>=128).
// Both tiles read gZ; sign of W's first K-half applied by XOR-negating the
// A fragments on k-steps 0..7.
//   A @0 (64*528=33792) | B @33792 ; total 67584 B.
// ---------------------------------------------------------------------------
#define ROWB   528
#define OFF_B  33792
#define SMEM_BYTES 67584

__global__ void __launch_bounds__(256, 2)
gemm_kernel(float* __restrict__ out) {
    extern __shared__ __align__(16) char smem[];
    __shared__ float s_cj[64];

    const int tid = threadIdx.x;
    const int wid = tid >> 5;
    const int lid = tid & 31;
    const int wm  = wid & 1;           // m offset wm*32
    const int wn  = wid >> 1;          // n offset wn*16
    const int i0  = blockIdx.y * 64;
    const int j0  = blockIdx.x * 64;
    const uint32_t sb = smem_u32(smem);

    // ---- stage full K in 2 commit groups (k<128, then k>=128) ----
#pragma unroll
    for (int gph = 0; gph < 2; gph++) {
#pragma unroll
        for (int i = tid; i < 2048; i += 256) {
            const int t  = i >> 10;            // 0 = A tile, 1 = B tile
            const int r  = (i >> 4) & 63;
            const int cc = i & 15;
            const int src_row = (t ? j0 : i0) + r;
            CP16(sb + t * OFF_B + r * ROWB + gph * 256 + cc * 16,
                 gZ + src_row * K2 + gph * 128 + cc * 8);
        }
        CP_COMMIT();
    }

    if (tid < 64) s_cj[tid] = gC[j0 + tid];

    // ---- per-lane ldmatrix base addresses ----
    const uint32_t arow = lid & 15;
    const uint32_t acol = (lid >> 4) * 16;            // bytes
    const uint32_t brow = (lid & 7) | (((lid >> 4) & 1) << 3);
    const uint32_t bcol = ((lid >> 3) & 1) * 16;
    const uint32_t aAd = sb + (wm * 32 + arow) * ROWB + acol;
    const uint32_t bAd = sb + OFF_B + (wn * 16 + brow) * ROWB + bcol;

    float acc[2][2][4] = {};
    uint32_t F[2][12];   // [set][ a0..7 | b0..3 ]

    auto ldf = [&](uint32_t* f, int ks) {
        const uint32_t ko = (uint32_t)ks * 32;
        LDSM4(f[0], f[1], f[2],  f[3],  aAd + ko);
        LDSM4(f[4], f[5], f[6],  f[7],  aAd + ko + 16 * ROWB);
        LDSM4(f[8], f[9], f[10], f[11], bAd + ko);
        if (ks < 8) {   // W's first K-half is -Z: negate A frags (packed fp16)
#pragma unroll
            for (int q = 0; q < 8; q++) f[q] ^= 0x80008000u;
        }
    };
    auto domma = [&](uint32_t* f) {
#pragma unroll
        for (int mf = 0; mf < 2; mf++) {
            uint32_t* a = f + mf * 4;
#pragma unroll
            for (int nf = 0; nf < 2; nf++)
                mma_f16(acc[mf][nf], a[0], a[1], a[2], a[3],
                        f[8 + nf * 2], f[9 + nf * 2]);
        }
    };

    // ---- k-steps 0..7 (group 0 resident) ----
    CP_WAIT(1);
    __syncthreads();
    ldf(F[0], 0);
#pragma unroll
    for (int ks = 0; ks < 7; ks++) {
        ldf(F[(ks + 1) & 1], ks + 1);
        domma(F[ks & 1]);
    }
    domma(F[1]);

    // ---- k-steps 8..15 ----
    CP_WAIT(0);
    __syncthreads();
    ldf(F[0], 8);
#pragma unroll
    for (int ks = 8; ks < 15; ks++) {
        ldf(F[(ks + 1) & 1], ks + 1);
        domma(F[ks & 1]);
    }
    domma(F[1]);

    // ---- epilogue: out[i][j] = (i==j) ? 1 : DIM / (c_i + c_j + S_ij) ----
    const int g = lid >> 2;
    const int t = lid & 3;
#pragma unroll
    for (int mf = 0; mf < 2; mf++) {
        const int ia = i0 + wm * 32 + mf * 16 + g;
        const int ib = ia + 8;
        const float cia = gC[ia];
        const float cib = gC[ib];
#pragma unroll
        for (int nf = 0; nf < 2; nf++) {
            const int jc = wn * 16 + nf * 8 + t * 2;
            const int j  = j0 + jc;
            const float cj0 = s_cj[jc];
            const float cj1 = s_cj[jc + 1];
            const float* s = acc[mf][nf];

            float v00 = (ia == j)     ? 1.0f : __fdividef((float)DIM, cia + cj0 + s[0]);
            float v01 = (ia == j + 1) ? 1.0f : __fdividef((float)DIM, cia + cj1 + s[1]);
            float v10 = (ib == j)     ? 1.0f : __fdividef((float)DIM, cib + cj0 + s[2]);
            float v11 = (ib == j + 1) ? 1.0f : __fdividef((float)DIM, cib + cj1 + s[3]);

            *(float2*)&out[ia * BSZ + j] = make_float2(v00, v01);
            *(float2*)&out[ib * BSZ + j] = make_float2(v10, v11);
        }
    }
}

// ---------------------------------------------------------------------------
extern "C" void kernel_launch(void* const* d_in, const int* in_sizes, int n_in,
                              void* d_out, int out_size) {
    const float* x  = (const float*)d_in[0];
    const float* dc = (const float*)d_in[1];
    const float* ap = (const float*)d_in[2];
    float* out = (float*)d_out;

    cudaFuncSetAttribute(gemm_kernel, cudaFuncAttributeMaxDynamicSharedMemorySize, SMEM_BYTES);

    prep_kernel<<<128, 256>>>(x, dc, ap);
    gemm_kernel<<<dim3(16, 16), 256, SMEM_BYTES>>>(out);
}